// round 1
// baseline (speedup 1.0000x reference)
#include <cuda_runtime.h>

// Problem constants
#define BSZ   8192
#define D     256
#define H1    50
#define H1P   64      // padded
#define H2    32
#define O     18
#define ROWS  32              // rows per main-kernel block
#define NB2   (BSZ/ROWS)      // 256 main blocks
#define TPB   256
#define NB1   64              // ysum partial blocks
#define YROWS (BSZ/NB1)       // 128

// Shared memory layout (floats) for k_main
#define OFF_W1  0               // 256*64 = 16384
#define OFF_X   16384           // 256*33 = 8448  (stride-33 transposed x tile)
#define OFF_W2  24832           // 50*32  = 1600
#define OFF_W3  26432           // 32*18  = 576
#define OFF_B1  27008           // 64
#define OFF_B2  27072           // 32
#define OFF_B3  27104           // 32
#define OFF_H1  27136           // 32*50  = 1600
#define OFF_H2  28736           // 32*32  = 1024
#define OFF_WU  29760           // 32*18  = 576
#define OFF_LD  30336           // 32
#define SMEM_FLOATS 30368
#define SMEM_BYTES  (SMEM_FLOATS * 4)

// Deterministic partial-sum scratch (device globals — no allocation)
__device__ float g_pY[NB1][O];        // y column-sum partials
__device__ float g_pB[NB2][O + 1];    // [Σ wu over block rows (18), Σ log_denom (1)]

__device__ __forceinline__ float sigmoidf(float v) {
    return 1.0f / (1.0f + __expf(-v));
}

// ---------------------------------------------------------------------------
// Kernel 1: partial column sums of y  (deterministic tree reduction)
// ---------------------------------------------------------------------------
__global__ void k_ysum(const float* __restrict__ y) {
    __shared__ float s[YROWS][O];
    const int t = threadIdx.x;             // blockDim = 128
    const int base = blockIdx.x * YROWS;
    const float* yr = y + (size_t)(base + t) * O;
#pragma unroll
    for (int j = 0; j < O; j++) s[t][j] = yr[j];
    __syncthreads();
#pragma unroll
    for (int st = YROWS / 2; st >= 1; st >>= 1) {
        if (t < st) {
#pragma unroll
            for (int j = 0; j < O; j++) s[t][j] += s[t + st][j];
        }
        __syncthreads();
    }
    if (t < O) g_pY[blockIdx.x][t] = s[0][t];
}

// ---------------------------------------------------------------------------
// Kernel 2: fused MLP + W_user store + factorized logsumexp + block partials
// ---------------------------------------------------------------------------
__global__ __launch_bounds__(TPB, 1) void k_main(
    const float* __restrict__ x,
    const float* __restrict__ W1, const float* __restrict__ b1,
    const float* __restrict__ W2, const float* __restrict__ b2,
    const float* __restrict__ W3, const float* __restrict__ b3,
    float* __restrict__ out)
{
    extern __shared__ float sm[];
    float* sW1 = sm + OFF_W1;
    float* sX  = sm + OFF_X;
    float* sW2 = sm + OFF_W2;
    float* sW3 = sm + OFF_W3;
    float* sb1 = sm + OFF_B1;
    float* sb2 = sm + OFF_B2;
    float* sb3 = sm + OFF_B3;
    float* sH1 = sm + OFF_H1;
    float* sH2 = sm + OFF_H2;
    float* sWU = sm + OFF_WU;
    float* sLD = sm + OFF_LD;

    const int tid  = threadIdx.x;
    const int row0 = blockIdx.x * ROWS;

    // ---- Stage 0: cooperative loads ----
    // W1 zero-padded to [256][64]
    for (int i = tid; i < D * H1P; i += TPB) {
        const int k = i >> 6, u = i & 63;
        sW1[i] = (u < H1) ? W1[k * H1 + u] : 0.0f;
    }
    // x tile transposed: sX[k*33 + r] = x[row0+r][k]  (coalesced gmem reads)
    for (int i = tid; i < ROWS * D; i += TPB) {
        const int r = i >> 8, k = i & 255;
        sX[k * 33 + r] = x[(size_t)(row0 + r) * D + k];
    }
    for (int i = tid; i < H1 * H2; i += TPB) sW2[i] = W2[i];
    for (int i = tid; i < H2 * O;  i += TPB) sW3[i] = W3[i];
    if (tid < H1)                 sb1[tid] = b1[tid];
    else if (tid < H1 + H2)       sb2[tid - H1] = b2[tid - H1];
    else if (tid < H1 + H2 + O)   sb3[tid - H1 - H2] = b3[tid - H1 - H2];
    __syncthreads();

    // ---- Stage 1: layer 1 GEMM (32 rows x 64 padded units, K=256) ----
    // thread = (tc: unit pair, tr: 4-row group); x loads are warp-broadcast
    {
        const int tc = tid & 31;
        const int r0 = (tid >> 5) * 4;
        float a00 = 0.f, a01 = 0.f, a10 = 0.f, a11 = 0.f;
        float a20 = 0.f, a21 = 0.f, a30 = 0.f, a31 = 0.f;
        const float2* w1v = reinterpret_cast<const float2*>(sW1);
#pragma unroll 8
        for (int k = 0; k < D; k++) {
            const float2 w = w1v[k * 32 + tc];
            const float* xk = sX + k * 33 + r0;
            const float x0 = xk[0], x1 = xk[1], x2 = xk[2], x3 = xk[3];
            a00 = fmaf(x0, w.x, a00); a01 = fmaf(x0, w.y, a01);
            a10 = fmaf(x1, w.x, a10); a11 = fmaf(x1, w.y, a11);
            a20 = fmaf(x2, w.x, a20); a21 = fmaf(x2, w.y, a21);
            a30 = fmaf(x3, w.x, a30); a31 = fmaf(x3, w.y, a31);
        }
        const int u0 = 2 * tc;
        if (u0 < H1) {
            const float bb = sb1[u0];
            sH1[(r0 + 0) * H1 + u0] = sigmoidf(a00 + bb);
            sH1[(r0 + 1) * H1 + u0] = sigmoidf(a10 + bb);
            sH1[(r0 + 2) * H1 + u0] = sigmoidf(a20 + bb);
            sH1[(r0 + 3) * H1 + u0] = sigmoidf(a30 + bb);
        }
        if (u0 + 1 < H1) {
            const float bb = sb1[u0 + 1];
            sH1[(r0 + 0) * H1 + u0 + 1] = sigmoidf(a01 + bb);
            sH1[(r0 + 1) * H1 + u0 + 1] = sigmoidf(a11 + bb);
            sH1[(r0 + 2) * H1 + u0 + 1] = sigmoidf(a21 + bb);
            sH1[(r0 + 3) * H1 + u0 + 1] = sigmoidf(a31 + bb);
        }
    }
    __syncthreads();

    // ---- Stage 2: layer 2 (32 rows x 32 units, K=50) ----
    {
        const int u  = tid & 31;
        const int rg = tid >> 5;   // rows rg, rg+8, rg+16, rg+24
        float a0 = sb2[u], a1 = a0, a2 = a0, a3 = a0;
#pragma unroll
        for (int k = 0; k < H1; k++) {
            const float w = sW2[k * H2 + u];
            a0 = fmaf(sH1[(rg +  0) * H1 + k], w, a0);
            a1 = fmaf(sH1[(rg +  8) * H1 + k], w, a1);
            a2 = fmaf(sH1[(rg + 16) * H1 + k], w, a2);
            a3 = fmaf(sH1[(rg + 24) * H1 + k], w, a3);
        }
        sH2[(rg +  0) * H2 + u] = sigmoidf(a0);
        sH2[(rg +  8) * H2 + u] = sigmoidf(a1);
        sH2[(rg + 16) * H2 + u] = sigmoidf(a2);
        sH2[(rg + 24) * H2 + u] = sigmoidf(a3);
    }
    __syncthreads();

    // ---- Stage 3: layer 3 (32 rows x 18 units, K=32) + store W_user ----
    {
        const int w = tid >> 5, l = tid & 31;
        if (l < O) {
#pragma unroll
            for (int rr = 0; rr < 4; rr++) {
                const int r = w * 4 + rr;
                float a = sb3[l];
#pragma unroll
                for (int k = 0; k < H2; k++)
                    a = fmaf(sH2[r * H2 + k], sW3[k * O + l], a);
                sWU[r * O + l] = a;
                out[(size_t)(row0 + r) * O + l] = a;
            }
        }
    }
    __syncthreads();

    // ---- Stage 4: factorized log-denominator per row ----
    // cases = Cartesian one-hots (2,4,4,8) => logsumexp factorizes per group
    if (tid < ROWS) {
        const float* wu = sWU + tid * O;
        float ld = 0.f;
        {   // group [0,2)
            const float m = fmaxf(wu[0], wu[1]);
            ld += m + __logf(__expf(wu[0] - m) + __expf(wu[1] - m));
        }
        {   // group [2,6)
            const float m = fmaxf(fmaxf(wu[2], wu[3]), fmaxf(wu[4], wu[5]));
            ld += m + __logf(__expf(wu[2] - m) + __expf(wu[3] - m) +
                             __expf(wu[4] - m) + __expf(wu[5] - m));
        }
        {   // group [6,10)
            const float m = fmaxf(fmaxf(wu[6], wu[7]), fmaxf(wu[8], wu[9]));
            ld += m + __logf(__expf(wu[6] - m) + __expf(wu[7] - m) +
                             __expf(wu[8] - m) + __expf(wu[9] - m));
        }
        {   // group [10,18)
            float m = wu[10];
#pragma unroll
            for (int j = 11; j < 18; j++) m = fmaxf(m, wu[j]);
            float s = 0.f;
#pragma unroll
            for (int j = 10; j < 18; j++) s += __expf(wu[j] - m);
            ld += m + __logf(s);
        }
        sLD[tid] = ld;
    }
    __syncthreads();

    // ---- Stage 5: deterministic block partials ----
    if (tid < O) {
        float s = 0.f;
#pragma unroll
        for (int r = 0; r < ROWS; r++) s += sWU[r * O + tid];
        g_pB[blockIdx.x][tid] = s;
    } else if (tid == O) {
        float s = 0.f;
#pragma unroll
        for (int r = 0; r < ROWS; r++) s += sLD[r];
        g_pB[blockIdx.x][O] = s;
    }
}

// ---------------------------------------------------------------------------
// Kernel 3: final combine  loss = -( dot(Σwu, Σy) - Σ log_denom )
// ---------------------------------------------------------------------------
__global__ void k_final(float* __restrict__ out) {
    __shared__ float ysum[O], wusum[O];
    const int t = threadIdx.x;  // 32 threads
    if (t < O) {
        float s = 0.f;
        for (int b = 0; b < NB1; b++) s += g_pY[b][t];
        ysum[t] = s;
        float s2 = 0.f;
        for (int b = 0; b < NB2; b++) s2 += g_pB[b][t];
        wusum[t] = s2;
    }
    __syncthreads();
    if (t == 0) {
        float ldsum = 0.f;
        for (int b = 0; b < NB2; b++) ldsum += g_pB[b][O];
        float dot = 0.f;
        for (int j = 0; j < O; j++) dot += wusum[j] * ysum[j];
        out[(size_t)BSZ * O] = -(dot - ldsum);
    }
}

// ---------------------------------------------------------------------------
extern "C" void kernel_launch(void* const* d_in, const int* in_sizes, int n_in,
                              void* d_out, int out_size) {
    const float* x  = (const float*)d_in[0];
    const float* y  = (const float*)d_in[1];
    const float* W1 = (const float*)d_in[2];
    const float* b1 = (const float*)d_in[3];
    const float* W2 = (const float*)d_in[4];
    const float* b2 = (const float*)d_in[5];
    const float* W3 = (const float*)d_in[6];
    const float* b3 = (const float*)d_in[7];
    float* out = (float*)d_out;

    cudaFuncSetAttribute(k_main, cudaFuncAttributeMaxDynamicSharedMemorySize,
                         SMEM_BYTES);

    k_ysum<<<NB1, YROWS>>>(y);
    k_main<<<NB2, TPB, SMEM_BYTES>>>(x, W1, b1, W2, b2, W3, b3, out);
    k_final<<<1, 32>>>(out);
}

// round 2
// speedup vs baseline: 1.5959x; 1.5959x over previous
#include <cuda_runtime.h>

// Problem constants
#define BSZ   8192
#define D     256
#define H1    50
#define H1P   64
#define H2    32
#define O     18
#define ROWS  64              // rows per main-kernel block
#define NB2   (BSZ/ROWS)      // 128 main blocks -> single wave on 148 SMs
#define TPB   512
#define XS    260             // x smem row stride (floats), 16B-multiple
#define PBC   (O + 1 + O)     // partial cols: [sum_wu(18), sum_ld(1), sum_y(18)] = 37

// Shared memory layout (floats)
#define OFF_W1  0                        // 256*64 = 16384
#define OFF_X   16384                    // 64*260 = 16640
#define OFF_W2  (OFF_X + ROWS*XS)        // 33024, 1600
#define OFF_W3  (OFF_W2 + H1*H2)         // 34624, 576
#define OFF_B1  (OFF_W3 + H2*O)          // 35200, 64
#define OFF_B2  (OFF_B1 + 64)            // 35264, 32
#define OFF_B3  (OFF_B2 + 32)            // 35296, 32
#define OFF_H1  (OFF_B3 + 32)            // 35328, 64*50 = 3200
#define OFF_H2  (OFF_H1 + ROWS*H1)       // 38528, 64*32 = 2048
#define OFF_WU  (OFF_H2 + ROWS*H2)       // 40576, 64*18 = 1152
#define OFF_LD  (OFF_WU + ROWS*O)        // 41728, 64
#define OFF_Y   (OFF_LD + ROWS)          // 41792, 64*18 = 1152
#define SMEM_FLOATS (OFF_Y + ROWS*O)     // 42944
#define SMEM_BYTES  (SMEM_FLOATS * 4)    // 171776

// Deterministic partial-sum scratch
__device__ float g_pB[NB2][PBC];

__device__ __forceinline__ float sigmoidf(float v) {
    return 1.0f / (1.0f + __expf(-v));
}

// ---------------------------------------------------------------------------
// Main fused kernel: MLP + W_user + factorized logsumexp + block partials
// ---------------------------------------------------------------------------
__global__ __launch_bounds__(TPB, 1) void k_main(
    const float* __restrict__ x,  const float* __restrict__ y,
    const float* __restrict__ W1, const float* __restrict__ b1,
    const float* __restrict__ W2, const float* __restrict__ b2,
    const float* __restrict__ W3, const float* __restrict__ b3,
    float* __restrict__ out)
{
    extern __shared__ float sm[];
    float* sW1 = sm + OFF_W1;
    float* sX  = sm + OFF_X;
    float* sW2 = sm + OFF_W2;
    float* sW3 = sm + OFF_W3;
    float* sb1 = sm + OFF_B1;
    float* sb2 = sm + OFF_B2;
    float* sb3 = sm + OFF_B3;
    float* sH1 = sm + OFF_H1;
    float* sH2 = sm + OFF_H2;
    float* sWU = sm + OFF_WU;
    float* sLD = sm + OFF_LD;
    float* sY  = sm + OFF_Y;

    const int tid  = threadIdx.x;
    const int row0 = blockIdx.x * ROWS;

    // ---- Stage 0: cooperative staging ----
    // W1 zero-padded to [256][64]
    for (int i = tid; i < D * H1P; i += TPB) {
        const int k = i >> 6, u = i & 63;
        sW1[i] = (u < H1) ? W1[k * H1 + u] : 0.0f;
    }
    // x tile row-major, float4 both sides (coalesced, conflict-free)
    {
        const float4* xg = reinterpret_cast<const float4*>(x + (size_t)row0 * D);
#pragma unroll
        for (int i = tid; i < ROWS * (D / 4); i += TPB) {
            const int r = i >> 6, c = i & 63;
            reinterpret_cast<float4*>(sX + r * XS)[c] = xg[r * 64 + c];
        }
    }
    // y tile (rows contiguous -> linear copy)
    for (int i = tid; i < ROWS * O; i += TPB)
        sY[i] = y[(size_t)row0 * O + i];
    for (int i = tid; i < H1 * H2; i += TPB) sW2[i] = W2[i];
    for (int i = tid; i < H2 * O;  i += TPB) sW3[i] = W3[i];
    if (tid < H1)                 sb1[tid] = b1[tid];
    else if (tid < H1 + H2)       sb2[tid - H1] = b2[tid - H1];
    else if (tid < H1 + H2 + O)   sb3[tid - H1 - H2] = b3[tid - H1 - H2];
    __syncthreads();

    // ---- Stage 1: layer 1 GEMM (64 rows x 64 padded units, K=256) ----
    // thread = (tc: unit pair, rg: 4-row group); x loads warp-broadcast float4
    {
        const int tc = tid & 31;          // unit pair -> u0 = 2*tc
        const int rg = tid >> 5;          // 0..15 -> rows rg*4 .. rg*4+3
        const float* xb = sX + rg * 4 * XS;
        const float2* w1v = reinterpret_cast<const float2*>(sW1);

        float a[4][2];
#pragma unroll
        for (int r = 0; r < 4; r++) { a[r][0] = 0.f; a[r][1] = 0.f; }

#pragma unroll 4
        for (int k = 0; k < D; k += 4) {
            float4 xv[4];
#pragma unroll
            for (int r = 0; r < 4; r++)
                xv[r] = *reinterpret_cast<const float4*>(xb + r * XS + k);
            float2 wv[4];
#pragma unroll
            for (int kk = 0; kk < 4; kk++)
                wv[kk] = w1v[(k + kk) * 32 + tc];
#pragma unroll
            for (int r = 0; r < 4; r++) {
                a[r][0] = fmaf(xv[r].x, wv[0].x, a[r][0]);
                a[r][1] = fmaf(xv[r].x, wv[0].y, a[r][1]);
                a[r][0] = fmaf(xv[r].y, wv[1].x, a[r][0]);
                a[r][1] = fmaf(xv[r].y, wv[1].y, a[r][1]);
                a[r][0] = fmaf(xv[r].z, wv[2].x, a[r][0]);
                a[r][1] = fmaf(xv[r].z, wv[2].y, a[r][1]);
                a[r][0] = fmaf(xv[r].w, wv[3].x, a[r][0]);
                a[r][1] = fmaf(xv[r].w, wv[3].y, a[r][1]);
            }
        }
        const int u0 = 2 * tc;
        if (u0 < H1) {   // u0 even <= 48, so u0+1 <= 49 < H1 too
            const float bb0 = sb1[u0], bb1 = sb1[u0 + 1];
#pragma unroll
            for (int r = 0; r < 4; r++) {
                sH1[(rg * 4 + r) * H1 + u0]     = sigmoidf(a[r][0] + bb0);
                sH1[(rg * 4 + r) * H1 + u0 + 1] = sigmoidf(a[r][1] + bb1);
            }
        }
    }
    __syncthreads();

    // ---- Stage 2: layer 2 (64 rows x 32 units, K=50) ----
    {
        const int u  = tid & 31;
        const int rg = tid >> 5;   // rows rg, rg+16, rg+32, rg+48
        float a0 = sb2[u], a1 = a0, a2 = a0, a3 = a0;
#pragma unroll
        for (int k = 0; k < H1; k++) {
            const float w = sW2[k * H2 + u];
            a0 = fmaf(sH1[(rg +  0) * H1 + k], w, a0);
            a1 = fmaf(sH1[(rg + 16) * H1 + k], w, a1);
            a2 = fmaf(sH1[(rg + 32) * H1 + k], w, a2);
            a3 = fmaf(sH1[(rg + 48) * H1 + k], w, a3);
        }
        sH2[(rg +  0) * H2 + u] = sigmoidf(a0);
        sH2[(rg + 16) * H2 + u] = sigmoidf(a1);
        sH2[(rg + 32) * H2 + u] = sigmoidf(a2);
        sH2[(rg + 48) * H2 + u] = sigmoidf(a3);
    }
    __syncthreads();

    // ---- Stage 3: layer 3 (64 rows x 18 units, K=32) + store W_user ----
    {
        const int w = tid >> 5, l = tid & 31;
        if (l < O) {
#pragma unroll
            for (int rr = 0; rr < 4; rr++) {
                const int r = w * 4 + rr;
                float a = sb3[l];
#pragma unroll
                for (int k = 0; k < H2; k++)
                    a = fmaf(sH2[r * H2 + k], sW3[k * O + l], a);
                sWU[r * O + l] = a;
                out[(size_t)(row0 + r) * O + l] = a;
            }
        }
    }
    __syncthreads();

    // ---- Stage 4: factorized log-denominator per row ----
    // cases = Cartesian one-hots (2,4,4,8) => logsumexp factorizes per group
    if (tid < ROWS) {
        const float* wu = sWU + tid * O;
        float ld = 0.f;
        {
            const float m = fmaxf(wu[0], wu[1]);
            ld += m + __logf(__expf(wu[0] - m) + __expf(wu[1] - m));
        }
        {
            const float m = fmaxf(fmaxf(wu[2], wu[3]), fmaxf(wu[4], wu[5]));
            ld += m + __logf(__expf(wu[2] - m) + __expf(wu[3] - m) +
                             __expf(wu[4] - m) + __expf(wu[5] - m));
        }
        {
            const float m = fmaxf(fmaxf(wu[6], wu[7]), fmaxf(wu[8], wu[9]));
            ld += m + __logf(__expf(wu[6] - m) + __expf(wu[7] - m) +
                             __expf(wu[8] - m) + __expf(wu[9] - m));
        }
        {
            float m = wu[10];
#pragma unroll
            for (int j = 11; j < 18; j++) m = fmaxf(m, wu[j]);
            float s = 0.f;
#pragma unroll
            for (int j = 10; j < 18; j++) s += __expf(wu[j] - m);
            ld += m + __logf(s);
        }
        sLD[tid] = ld;
    }
    __syncthreads();

    // ---- Stage 5: deterministic block partials ----
    if (tid < O) {                         // sum W_user columns
        float s = 0.f;
#pragma unroll
        for (int r = 0; r < ROWS; r++) s += sWU[r * O + tid];
        g_pB[blockIdx.x][tid] = s;
    } else if (tid == O) {                 // sum log_denom
        float s = 0.f;
#pragma unroll
        for (int r = 0; r < ROWS; r++) s += sLD[r];
        g_pB[blockIdx.x][O] = s;
    } else if (tid >= 32 && tid < 32 + O) {  // sum y columns
        const int j = tid - 32;
        float s = 0.f;
#pragma unroll
        for (int r = 0; r < ROWS; r++) s += sY[r * O + j];
        g_pB[blockIdx.x][O + 1 + j] = s;
    }
}

// ---------------------------------------------------------------------------
// Final combine  loss = -( dot(Σwu, Σy) - Σ log_denom )
// ---------------------------------------------------------------------------
__global__ void k_final(float* __restrict__ out) {
    __shared__ float part[8][PBC];
    __shared__ float tot[PBC];
    const int tid = threadIdx.x;           // 512 threads
    const int j   = tid & 63;
    const int seg = tid >> 6;              // 8 segments x 16 blocks
    if (j < PBC) {
        float s = 0.f;
        const int b0 = seg * (NB2 / 8);
#pragma unroll
        for (int b = 0; b < NB2 / 8; b++) s += g_pB[b0 + b][j];
        part[seg][j] = s;
    }
    __syncthreads();
    if (tid < PBC) {
        float s = 0.f;
#pragma unroll
        for (int sg = 0; sg < 8; sg++) s += part[sg][tid];
        tot[tid] = s;
    }
    __syncthreads();
    if (tid == 0) {
        float dot = 0.f;
#pragma unroll
        for (int jj = 0; jj < O; jj++) dot += tot[jj] * tot[O + 1 + jj];
        out[(size_t)BSZ * O] = -(dot - tot[O]);
    }
}

// ---------------------------------------------------------------------------
extern "C" void kernel_launch(void* const* d_in, const int* in_sizes, int n_in,
                              void* d_out, int out_size) {
    const float* x  = (const float*)d_in[0];
    const float* y  = (const float*)d_in[1];
    const float* W1 = (const float*)d_in[2];
    const float* b1 = (const float*)d_in[3];
    const float* W2 = (const float*)d_in[4];
    const float* b2 = (const float*)d_in[5];
    const float* W3 = (const float*)d_in[6];
    const float* b3 = (const float*)d_in[7];
    float* out = (float*)d_out;

    cudaFuncSetAttribute(k_main, cudaFuncAttributeMaxDynamicSharedMemorySize,
                         SMEM_BYTES);

    k_main<<<NB2, TPB, SMEM_BYTES>>>(x, y, W1, b1, W2, b2, W3, b3, out);
    k_final<<<1, TPB>>>(out);
}

// round 3
// speedup vs baseline: 1.6063x; 1.0065x over previous
#include <cuda_runtime.h>

// Problem constants
#define BSZ   8192
#define D     256
#define H1    50
#define H1P   64
#define H2    32
#define O     18
#define ROWS  64              // rows per main-kernel block
#define NB2   (BSZ/ROWS)      // 128 main blocks -> single wave on 148 SMs
#define TPB   512
#define XS    260             // x smem row stride (floats), 16B-multiple
#define PBC   (O + 1 + O)     // partial cols: [sum_wu(18), sum_ld(1), sum_y(18)] = 37

// Shared memory layout (floats)
#define OFF_W1  0                        // 256*64 = 16384
#define OFF_X   16384                    // 64*260 = 16640
#define OFF_W2  (OFF_X + ROWS*XS)        // 1600
#define OFF_W3  (OFF_W2 + H1*H2)         // 576
#define OFF_B1  (OFF_W3 + H2*O)          // 64
#define OFF_B2  (OFF_B1 + 64)            // 32
#define OFF_B3  (OFF_B2 + 32)            // 32
#define OFF_H1  (OFF_B3 + 32)            // 64*50 = 3200
#define OFF_H2  (OFF_H1 + ROWS*H1)       // 64*32 = 2048
#define OFF_WU  (OFF_H2 + ROWS*H2)       // 64*18 = 1152
#define OFF_LD  (OFF_WU + ROWS*O)        // 64
#define OFF_Y   (OFF_LD + ROWS)          // 64*18 = 1152
#define SMEM_FLOATS (OFF_Y + ROWS*O)
#define SMEM_BYTES  (SMEM_FLOATS * 4)    // ~172KB

// Deterministic partial-sum scratch + completion counter
__device__ float g_pB[NB2][PBC];
__device__ int   g_count = 0;

__device__ __forceinline__ float sigmoidf(float v) {
    return 1.0f / (1.0f + __expf(-v));
}

// ---------------------------------------------------------------------------
// Single fused kernel: MLP + W_user + factorized logsumexp + partials + loss
// ---------------------------------------------------------------------------
__global__ __launch_bounds__(TPB, 1) void k_main(
    const float* __restrict__ x,  const float* __restrict__ y,
    const float* __restrict__ W1, const float* __restrict__ b1,
    const float* __restrict__ W2, const float* __restrict__ b2,
    const float* __restrict__ W3, const float* __restrict__ b3,
    float* __restrict__ out)
{
    extern __shared__ float sm[];
    float* sW1 = sm + OFF_W1;
    float* sX  = sm + OFF_X;
    float* sW2 = sm + OFF_W2;
    float* sW3 = sm + OFF_W3;
    float* sb1 = sm + OFF_B1;
    float* sb2 = sm + OFF_B2;
    float* sb3 = sm + OFF_B3;
    float* sH1 = sm + OFF_H1;
    float* sH2 = sm + OFF_H2;
    float* sWU = sm + OFF_WU;
    float* sLD = sm + OFF_LD;
    float* sY  = sm + OFF_Y;
    __shared__ int sIsLast;

    const int tid  = threadIdx.x;
    const int row0 = blockIdx.x * ROWS;

    // ---- Stage 0: cooperative staging ----
    for (int i = tid; i < D * H1P; i += TPB) {
        const int k = i >> 6, u = i & 63;
        sW1[i] = (u < H1) ? W1[k * H1 + u] : 0.0f;
    }
    {
        const float4* xg = reinterpret_cast<const float4*>(x + (size_t)row0 * D);
#pragma unroll
        for (int i = tid; i < ROWS * (D / 4); i += TPB) {
            const int r = i >> 6, c = i & 63;
            reinterpret_cast<float4*>(sX + r * XS)[c] = xg[r * 64 + c];
        }
    }
    for (int i = tid; i < ROWS * O; i += TPB)
        sY[i] = y[(size_t)row0 * O + i];
    for (int i = tid; i < H1 * H2; i += TPB) sW2[i] = W2[i];
    for (int i = tid; i < H2 * O;  i += TPB) sW3[i] = W3[i];
    if (tid < H1)                 sb1[tid] = b1[tid];
    else if (tid < H1 + H2)       sb2[tid - H1] = b2[tid - H1];
    else if (tid < H1 + H2 + O)   sb3[tid - H1 - H2] = b3[tid - H1 - H2];
    __syncthreads();

    // ---- Stage 1: layer 1 GEMM (64 rows x 64 padded units, K=256) ----
    {
        const int tc = tid & 31;          // unit pair -> u0 = 2*tc
        const int rg = tid >> 5;          // 0..15 -> rows rg*4 .. rg*4+3
        const float* xb = sX + rg * 4 * XS;
        const float2* w1v = reinterpret_cast<const float2*>(sW1);

        float a[4][2];
#pragma unroll
        for (int r = 0; r < 4; r++) { a[r][0] = 0.f; a[r][1] = 0.f; }

#pragma unroll 4
        for (int k = 0; k < D; k += 4) {
            float4 xv[4];
#pragma unroll
            for (int r = 0; r < 4; r++)
                xv[r] = *reinterpret_cast<const float4*>(xb + r * XS + k);
            float2 wv[4];
#pragma unroll
            for (int kk = 0; kk < 4; kk++)
                wv[kk] = w1v[(k + kk) * 32 + tc];
#pragma unroll
            for (int r = 0; r < 4; r++) {
                a[r][0] = fmaf(xv[r].x, wv[0].x, a[r][0]);
                a[r][1] = fmaf(xv[r].x, wv[0].y, a[r][1]);
                a[r][0] = fmaf(xv[r].y, wv[1].x, a[r][0]);
                a[r][1] = fmaf(xv[r].y, wv[1].y, a[r][1]);
                a[r][0] = fmaf(xv[r].z, wv[2].x, a[r][0]);
                a[r][1] = fmaf(xv[r].z, wv[2].y, a[r][1]);
                a[r][0] = fmaf(xv[r].w, wv[3].x, a[r][0]);
                a[r][1] = fmaf(xv[r].w, wv[3].y, a[r][1]);
            }
        }
        const int u0 = 2 * tc;
        if (u0 < H1) {
            const float bb0 = sb1[u0], bb1 = sb1[u0 + 1];
#pragma unroll
            for (int r = 0; r < 4; r++) {
                sH1[(rg * 4 + r) * H1 + u0]     = sigmoidf(a[r][0] + bb0);
                sH1[(rg * 4 + r) * H1 + u0 + 1] = sigmoidf(a[r][1] + bb1);
            }
        }
    }
    __syncthreads();

    // ---- Stage 2: layer 2 (64 rows x 32 units, K=50) ----
    {
        const int u  = tid & 31;
        const int rg = tid >> 5;
        float a0 = sb2[u], a1 = a0, a2 = a0, a3 = a0;
#pragma unroll
        for (int k = 0; k < H1; k++) {
            const float w = sW2[k * H2 + u];
            a0 = fmaf(sH1[(rg +  0) * H1 + k], w, a0);
            a1 = fmaf(sH1[(rg + 16) * H1 + k], w, a1);
            a2 = fmaf(sH1[(rg + 32) * H1 + k], w, a2);
            a3 = fmaf(sH1[(rg + 48) * H1 + k], w, a3);
        }
        sH2[(rg +  0) * H2 + u] = sigmoidf(a0);
        sH2[(rg + 16) * H2 + u] = sigmoidf(a1);
        sH2[(rg + 32) * H2 + u] = sigmoidf(a2);
        sH2[(rg + 48) * H2 + u] = sigmoidf(a3);
    }
    __syncthreads();

    // ---- Stage 3: layer 3 (64 rows x 18 units, K=32) + store W_user ----
    {
        const int w = tid >> 5, l = tid & 31;
        if (l < O) {
#pragma unroll
            for (int rr = 0; rr < 4; rr++) {
                const int r = w * 4 + rr;
                float a = sb3[l];
#pragma unroll
                for (int k = 0; k < H2; k++)
                    a = fmaf(sH2[r * H2 + k], sW3[k * O + l], a);
                sWU[r * O + l] = a;
                out[(size_t)(row0 + r) * O + l] = a;
            }
        }
    }
    __syncthreads();

    // ---- Stage 4: factorized log-denominator per row ----
    if (tid < ROWS) {
        const float* wu = sWU + tid * O;
        float ld = 0.f;
        {
            const float m = fmaxf(wu[0], wu[1]);
            ld += m + __logf(__expf(wu[0] - m) + __expf(wu[1] - m));
        }
        {
            const float m = fmaxf(fmaxf(wu[2], wu[3]), fmaxf(wu[4], wu[5]));
            ld += m + __logf(__expf(wu[2] - m) + __expf(wu[3] - m) +
                             __expf(wu[4] - m) + __expf(wu[5] - m));
        }
        {
            const float m = fmaxf(fmaxf(wu[6], wu[7]), fmaxf(wu[8], wu[9]));
            ld += m + __logf(__expf(wu[6] - m) + __expf(wu[7] - m) +
                             __expf(wu[8] - m) + __expf(wu[9] - m));
        }
        {
            float m = wu[10];
#pragma unroll
            for (int j = 11; j < 18; j++) m = fmaxf(m, wu[j]);
            float s = 0.f;
#pragma unroll
            for (int j = 10; j < 18; j++) s += __expf(wu[j] - m);
            ld += m + __logf(s);
        }
        sLD[tid] = ld;
    }
    __syncthreads();

    // ---- Stage 5: deterministic block partials (L2-resident) ----
    if (tid < O) {
        float s = 0.f;
#pragma unroll
        for (int r = 0; r < ROWS; r++) s += sWU[r * O + tid];
        __stcg(&g_pB[blockIdx.x][tid], s);
    } else if (tid == O) {
        float s = 0.f;
#pragma unroll
        for (int r = 0; r < ROWS; r++) s += sLD[r];
        __stcg(&g_pB[blockIdx.x][O], s);
    } else if (tid >= 32 && tid < 32 + O) {
        const int j = tid - 32;
        float s = 0.f;
#pragma unroll
        for (int r = 0; r < ROWS; r++) s += sY[r * O + j];
        __stcg(&g_pB[blockIdx.x][O + 1 + j], s);
    }

    // ---- Stage 6: last-block final combine (fused, deterministic) ----
    __threadfence();
    __syncthreads();
    if (tid == 0) {
        const int old = atomicAdd(&g_count, 1);
        sIsLast = (old == NB2 - 1);
    }
    __syncthreads();
    if (!sIsLast) return;
    __threadfence();   // acquire: make all blocks' g_pB stores visible

    {
        // reuse smem (all prior uses complete within this block)
        float* part = sm;            // [8][PBC]
        float* tot  = sm + 8 * PBC;  // [PBC]
        const int j   = tid & 63;
        const int seg = tid >> 6;    // 8 segments x 16 blocks
        if (j < PBC) {
            float s = 0.f;
            const int b0 = seg * (NB2 / 8);
#pragma unroll
            for (int b = 0; b < NB2 / 8; b++)
                s += __ldcg(&g_pB[b0 + b][j]);
            part[seg * PBC + j] = s;
        }
        __syncthreads();
        if (tid < PBC) {
            float s = 0.f;
#pragma unroll
            for (int sg = 0; sg < 8; sg++) s += part[sg * PBC + tid];
            tot[tid] = s;
        }
        __syncthreads();
        if (tid == 0) {
            float dot = 0.f;
#pragma unroll
            for (int jj = 0; jj < O; jj++) dot += tot[jj] * tot[O + 1 + jj];
            out[(size_t)BSZ * O] = -(dot - tot[O]);
            g_count = 0;   // reset for next graph replay
        }
    }
}

// ---------------------------------------------------------------------------
extern "C" void kernel_launch(void* const* d_in, const int* in_sizes, int n_in,
                              void* d_out, int out_size) {
    const float* x  = (const float*)d_in[0];
    const float* y  = (const float*)d_in[1];
    const float* W1 = (const float*)d_in[2];
    const float* b1 = (const float*)d_in[3];
    const float* W2 = (const float*)d_in[4];
    const float* b2 = (const float*)d_in[5];
    const float* W3 = (const float*)d_in[6];
    const float* b3 = (const float*)d_in[7];
    float* out = (float*)d_out;

    cudaFuncSetAttribute(k_main, cudaFuncAttributeMaxDynamicSharedMemorySize,
                         SMEM_BYTES);

    k_main<<<NB2, TPB, SMEM_BYTES>>>(x, y, W1, b1, W2, b2, W3, b3, out);
}

// round 4
// speedup vs baseline: 1.6970x; 1.0565x over previous
#include <cuda_runtime.h>

// Problem constants
#define BSZ   8192
#define D     256
#define H1    50
#define H1P   64
#define H2    32
#define O     18
#define ROWS  64              // rows per block
#define NB2   (BSZ/ROWS)      // 128 blocks -> single wave
#define TPB   256
#define XS    260             // x smem row stride (floats), 16B-multiple
#define PBC   (O + 1 + O)     // [sum_wu(18), sum_ld(1), sum_y(18)] = 37

// Shared memory layout (floats)
#define OFF_W1  0                        // 256*64 = 16384
#define OFF_X   16384                    // 64*260 = 16640
#define OFF_W2  (OFF_X + ROWS*XS)        // 1600
#define OFF_W3  (OFF_W2 + H1*H2)         // 576
#define OFF_B1  (OFF_W3 + H2*O)          // 64
#define OFF_B2  (OFF_B1 + 64)            // 32
#define OFF_B3  (OFF_B2 + 32)            // 32
#define OFF_H1  (OFF_B3 + 32)            // 64*50 = 3200
#define OFF_H2  (OFF_H1 + ROWS*H1)       // 64*32 = 2048
#define OFF_WU  (OFF_H2 + ROWS*H2)       // 64*18 = 1152
#define OFF_LD  (OFF_WU + ROWS*O)        // 64
#define OFF_Y   (OFF_LD + ROWS)          // 64*18 = 1152
#define SMEM_FLOATS (OFF_Y + ROWS*O)
#define SMEM_BYTES  (SMEM_FLOATS * 4)    // ~172KB

// Deterministic partial-sum scratch + completion counter
__device__ float g_pB[NB2][PBC];
__device__ int   g_count = 0;

__device__ __forceinline__ float sigmoidf(float v) {
    return 1.0f / (1.0f + __expf(-v));
}

// ---------------------------------------------------------------------------
// Single fused kernel
// ---------------------------------------------------------------------------
__global__ __launch_bounds__(TPB, 1) void k_main(
    const float* __restrict__ x,  const float* __restrict__ y,
    const float* __restrict__ W1, const float* __restrict__ b1,
    const float* __restrict__ W2, const float* __restrict__ b2,
    const float* __restrict__ W3, const float* __restrict__ b3,
    float* __restrict__ out)
{
    extern __shared__ float sm[];
    float* sW1 = sm + OFF_W1;
    float* sX  = sm + OFF_X;
    float* sW2 = sm + OFF_W2;
    float* sW3 = sm + OFF_W3;
    float* sb1 = sm + OFF_B1;
    float* sb2 = sm + OFF_B2;
    float* sb3 = sm + OFF_B3;
    float* sH1 = sm + OFF_H1;
    float* sH2 = sm + OFF_H2;
    float* sWU = sm + OFF_WU;
    float* sLD = sm + OFF_LD;
    float* sY  = sm + OFF_Y;
    __shared__ int sIsLast;

    const int tid  = threadIdx.x;
    const int row0 = blockIdx.x * ROWS;

    // ---- Stage 0: cooperative staging (vectorized) ----
    {   // W1 [256][50] -> padded [256][64], float2 both sides
        const float2* W1v = reinterpret_cast<const float2*>(W1);
        float2* sW1v = reinterpret_cast<float2*>(sW1);
        const float2 z2 = make_float2(0.f, 0.f);
#pragma unroll
        for (int i = tid; i < D * 32; i += TPB) {
            const int k = i >> 5, u2 = i & 31;
            sW1v[i] = (u2 < 25) ? W1v[k * 25 + u2] : z2;
        }
    }
    {   // x tile row-major float4
        const float4* xg = reinterpret_cast<const float4*>(x + (size_t)row0 * D);
#pragma unroll
        for (int i = tid; i < ROWS * (D / 4); i += TPB) {
            const int r = i >> 6, c = i & 63;
            reinterpret_cast<float4*>(sX + r * XS)[c] = xg[r * 64 + c];
        }
    }
    {   // y tile float2 (ROWS*O even)
        const float2* yg = reinterpret_cast<const float2*>(y + (size_t)row0 * O);
        float2* sYv = reinterpret_cast<float2*>(sY);
        for (int i = tid; i < ROWS * O / 2; i += TPB) sYv[i] = yg[i];
    }
    {   // W2 (1600 floats), W3 (576 floats) as float2
        const float2* W2v = reinterpret_cast<const float2*>(W2);
        float2* sW2v = reinterpret_cast<float2*>(sW2);
        for (int i = tid; i < H1 * H2 / 2; i += TPB) sW2v[i] = W2v[i];
        const float2* W3v = reinterpret_cast<const float2*>(W3);
        float2* sW3v = reinterpret_cast<float2*>(sW3);
        for (int i = tid; i < H2 * O / 2; i += TPB) sW3v[i] = W3v[i];
    }
    if (tid < H1)                 sb1[tid] = b1[tid];
    else if (tid < H1 + H2)       sb2[tid - H1] = b2[tid - H1];
    else if (tid < H1 + H2 + O)   sb3[tid - H1 - H2] = b3[tid - H1 - H2];
    __syncthreads();

    // ---- Stage 1: layer 1 GEMM, 4 rows x 4 units per thread, K=256 ----
    {
        const int tc = tid & 15;          // unit quad: u0 = 4*tc
        const int rg = tid >> 4;          // 0..15 -> rows rg*4..rg*4+3
        const float* xb = sX + rg * 4 * XS;
        const float* wb = sW1 + 4 * tc;

        float a[4][4];
#pragma unroll
        for (int r = 0; r < 4; r++)
#pragma unroll
            for (int j = 0; j < 4; j++) a[r][j] = 0.f;

#pragma unroll 2
        for (int k = 0; k < D; k += 4) {
            float4 xv[4];
#pragma unroll
            for (int r = 0; r < 4; r++)
                xv[r] = *reinterpret_cast<const float4*>(xb + r * XS + k);
            float4 wv[4];
#pragma unroll
            for (int kk = 0; kk < 4; kk++)
                wv[kk] = *reinterpret_cast<const float4*>(wb + (k + kk) * H1P);
#pragma unroll
            for (int r = 0; r < 4; r++) {
                a[r][0] = fmaf(xv[r].x, wv[0].x, a[r][0]);
                a[r][1] = fmaf(xv[r].x, wv[0].y, a[r][1]);
                a[r][2] = fmaf(xv[r].x, wv[0].z, a[r][2]);
                a[r][3] = fmaf(xv[r].x, wv[0].w, a[r][3]);
                a[r][0] = fmaf(xv[r].y, wv[1].x, a[r][0]);
                a[r][1] = fmaf(xv[r].y, wv[1].y, a[r][1]);
                a[r][2] = fmaf(xv[r].y, wv[1].z, a[r][2]);
                a[r][3] = fmaf(xv[r].y, wv[1].w, a[r][3]);
                a[r][0] = fmaf(xv[r].z, wv[2].x, a[r][0]);
                a[r][1] = fmaf(xv[r].z, wv[2].y, a[r][1]);
                a[r][2] = fmaf(xv[r].z, wv[2].z, a[r][2]);
                a[r][3] = fmaf(xv[r].z, wv[2].w, a[r][3]);
                a[r][0] = fmaf(xv[r].w, wv[3].x, a[r][0]);
                a[r][1] = fmaf(xv[r].w, wv[3].y, a[r][1]);
                a[r][2] = fmaf(xv[r].w, wv[3].z, a[r][2]);
                a[r][3] = fmaf(xv[r].w, wv[3].w, a[r][3]);
            }
        }
        const int u0 = 4 * tc;
#pragma unroll
        for (int j = 0; j < 4; j++) {
            const int u = u0 + j;
            if (u < H1) {
                const float bb = sb1[u];
#pragma unroll
                for (int r = 0; r < 4; r++)
                    sH1[(rg * 4 + r) * H1 + u] = sigmoidf(a[r][j] + bb);
            }
        }
    }
    __syncthreads();

    // ---- Stage 2: layer 2 (64 rows x 32 units, K=50), float2 over k ----
    {
        const int u  = tid & 31;
        const int rg = tid >> 5;   // 0..7, rows rg + 8*s
        float acc[8];
#pragma unroll
        for (int s = 0; s < 8; s++) acc[s] = sb2[u];
#pragma unroll
        for (int k = 0; k < H1; k += 2) {
            const float w0 = sW2[k * H2 + u];
            const float w1 = sW2[(k + 1) * H2 + u];
#pragma unroll
            for (int s = 0; s < 8; s++) {
                const float2 h = *reinterpret_cast<const float2*>(
                    sH1 + (rg + 8 * s) * H1 + k);
                acc[s] = fmaf(h.x, w0, fmaf(h.y, w1, acc[s]));
            }
        }
#pragma unroll
        for (int s = 0; s < 8; s++)
            sH2[(rg + 8 * s) * H2 + u] = sigmoidf(acc[s]);
    }
    __syncthreads();

    // ---- Stage 3: layer 3 (64 rows x 18 units, K=32) + store W_user ----
    {
        const int w = tid >> 5, l = tid & 31;
        if (l < O) {
#pragma unroll
            for (int rr = 0; rr < 8; rr++) {
                const int r = w * 8 + rr;
                float a = sb3[l];
#pragma unroll
                for (int k = 0; k < H2; k++)
                    a = fmaf(sH2[r * H2 + k], sW3[k * O + l], a);
                sWU[r * O + l] = a;
                out[(size_t)(row0 + r) * O + l] = a;
            }
        }
    }
    __syncthreads();

    // ---- Stage 4: factorized log-denominator per row ----
    if (tid < ROWS) {
        const float* wu = sWU + tid * O;
        float ld = 0.f;
        {
            const float m = fmaxf(wu[0], wu[1]);
            ld += m + __logf(__expf(wu[0] - m) + __expf(wu[1] - m));
        }
        {
            const float m = fmaxf(fmaxf(wu[2], wu[3]), fmaxf(wu[4], wu[5]));
            ld += m + __logf(__expf(wu[2] - m) + __expf(wu[3] - m) +
                             __expf(wu[4] - m) + __expf(wu[5] - m));
        }
        {
            const float m = fmaxf(fmaxf(wu[6], wu[7]), fmaxf(wu[8], wu[9]));
            ld += m + __logf(__expf(wu[6] - m) + __expf(wu[7] - m) +
                             __expf(wu[8] - m) + __expf(wu[9] - m));
        }
        {
            float m = wu[10];
#pragma unroll
            for (int j = 11; j < 18; j++) m = fmaxf(m, wu[j]);
            float s = 0.f;
#pragma unroll
            for (int j = 10; j < 18; j++) s += __expf(wu[j] - m);
            ld += m + __logf(s);
        }
        sLD[tid] = ld;
    }
    __syncthreads();

    // ---- Stage 5: deterministic block partials (L2-resident) ----
    if (tid < O) {
        float s = 0.f;
#pragma unroll
        for (int r = 0; r < ROWS; r++) s += sWU[r * O + tid];
        __stcg(&g_pB[blockIdx.x][tid], s);
    } else if (tid == O) {
        float s = 0.f;
#pragma unroll
        for (int r = 0; r < ROWS; r++) s += sLD[r];
        __stcg(&g_pB[blockIdx.x][O], s);
    } else if (tid >= 32 && tid < 32 + O) {
        const int j = tid - 32;
        float s = 0.f;
#pragma unroll
        for (int r = 0; r < ROWS; r++) s += sY[r * O + j];
        __stcg(&g_pB[blockIdx.x][O + 1 + j], s);
    }

    // ---- Stage 6: last-block final combine ----
    __threadfence();
    __syncthreads();
    if (tid == 0) {
        const int old = atomicAdd(&g_count, 1);
        sIsLast = (old == NB2 - 1);
    }
    __syncthreads();
    if (!sIsLast) return;
    __threadfence();   // acquire all blocks' g_pB stores

    {
        float* part = sm;            // [4][PBC]
        float* tot  = sm + 4 * PBC;  // [PBC]
        const int j   = tid & 63;
        const int seg = tid >> 6;    // 4 segments x 32 blocks
        if (j < PBC) {
            float s = 0.f;
            const int b0 = seg * (NB2 / 4);
#pragma unroll
            for (int b = 0; b < NB2 / 4; b++)
                s += __ldcg(&g_pB[b0 + b][j]);
            part[seg * PBC + j] = s;
        }
        __syncthreads();
        if (tid < PBC) {
            float s = 0.f;
#pragma unroll
            for (int sg = 0; sg < 4; sg++) s += part[sg * PBC + tid];
            tot[tid] = s;
        }
        __syncthreads();
        if (tid == 0) {
            float dot = 0.f;
#pragma unroll
            for (int jj = 0; jj < O; jj++) dot += tot[jj] * tot[O + 1 + jj];
            out[(size_t)BSZ * O] = -(dot - tot[O]);
            g_count = 0;   // reset for graph replay
        }
    }
}

// ---------------------------------------------------------------------------
extern "C" void kernel_launch(void* const* d_in, const int* in_sizes, int n_in,
                              void* d_out, int out_size) {
    const float* x  = (const float*)d_in[0];
    const float* y  = (const float*)d_in[1];
    const float* W1 = (const float*)d_in[2];
    const float* b1 = (const float*)d_in[3];
    const float* W2 = (const float*)d_in[4];
    const float* b2 = (const float*)d_in[5];
    const float* W3 = (const float*)d_in[6];
    const float* b3 = (const float*)d_in[7];
    float* out = (float*)d_out;

    cudaFuncSetAttribute(k_main, cudaFuncAttributeMaxDynamicSharedMemorySize,
                         SMEM_BYTES);

    k_main<<<NB2, TPB, SMEM_BYTES>>>(x, y, W1, b1, W2, b2, W3, b3, out);
}